// round 5
// baseline (speedup 1.0000x reference)
#include <cuda_runtime.h>
#include <cuda_bf16.h>
#include <math.h>
#include <stdlib.h>

// Problem constants (fixed by the reference)
#define NN 50000
#define NE 640000
#define NG 64
#define HD 128
#define INF 8
#define BN_EPS 1e-5f

// Best-effort eager module loading (harmless if inert on this stack).
__attribute__((constructor))
static void _set_eager_module_loading() {
    setenv("CUDA_MODULE_LOADING", "EAGER", 1);
}

// ---------------- scratch (static __device__; kept SMALL: ~54 MB total) ------
// bufA = h1, bufB = h2. h3 is pooled in-kernel and never materialized.
__device__ float g_bufA[NN * HD];          // 25.6 MB
__device__ float g_bufB[NN * HD];          // 25.6 MB
__device__ int   g_deg[NN];
__device__ int   g_rowptr[NN + 1];
__device__ int   g_cursor[NN];
__device__ int   g_col[NE];                // 2.56 MB
__device__ float g_pooled[NG * 384];

// Secondary best-effort eager load (no-op if registration hasn't run yet).
namespace {
struct TryEagerLoad {
    TryEagerLoad() {
        void* p = nullptr;
        cudaGetSymbolAddress(&p, g_bufA);
    }
};
static TryEagerLoad _try_eager_load;
}

// ---------------- init: zero degree counts + pooled accumulators -------------
__global__ void zero_kernel() {
    int i = blockIdx.x * blockDim.x + threadIdx.x;
    if (i < NN) g_deg[i] = 0;
    if (i < NG * 384) g_pooled[i] = 0.f;
}

// ---------------- CSR build ----------------
__global__ void count_kernel(const int* __restrict__ eidx) {
    int e = blockIdx.x * blockDim.x + threadIdx.x;
    if (e < NE) atomicAdd(&g_deg[eidx[NE + e]], 1);
}

// single-block scan over 50000 degrees -> rowptr, cursor(=exclusive)
__global__ void scan_kernel() {
    __shared__ int sdata[1024];
    __shared__ int s_carry;
    int tid = threadIdx.x;
    if (tid == 0) { s_carry = 0; g_rowptr[0] = 0; }
    __syncthreads();
    for (int base = 0; base < NN; base += 1024) {
        int i = base + tid;
        int v = (i < NN) ? g_deg[i] : 0;
        sdata[tid] = v;
        __syncthreads();
        int carry = s_carry;
        #pragma unroll
        for (int off = 1; off < 1024; off <<= 1) {
            int t = (tid >= off) ? sdata[tid - off] : 0;
            __syncthreads();
            sdata[tid] += t;
            __syncthreads();
        }
        int inc = sdata[tid] + carry;
        if (i < NN) {
            g_rowptr[i + 1] = inc;
            g_cursor[i] = inc - v;
        }
        __syncthreads();
        if (tid == 1023) s_carry = inc;
        __syncthreads();
    }
}

__global__ void fill_kernel(const int* __restrict__ eidx) {
    int e = blockIdx.x * blockDim.x + threadIdx.x;
    if (e < NE) {
        int src = eidx[e];
        int dst = eidx[NE + e];
        int pos = atomicAdd(&g_cursor[dst], 1);
        g_col[pos] = src;
    }
}

// ---------------- fused GIN layer --------------------------------------------
// Per 128-node tile (512 threads):
//   prologue: sIn[nl][:] = src[node] + sum_{nb in CSR(node)} src[nb]   (gather)
//   stage A : sT = relu(sIn @ W1 + b1)
//   stage B : o  = relu(sT @ W2 + b2)
//   epilogue: optional gmem write of o; pool o by (sorted) batch segment into
//             g_pooled[g*384 + SLICE + f] via atomicAdd.
// smem: sW(128x128) | sIn(128xFIN) | sT(128x128) | sBatch(128 ints)
template <int FIN, int SLICE, bool WRITE>
__global__ void __launch_bounds__(512)
mlp_fused(const float* __restrict__ src,
          const float* __restrict__ W1, const float* __restrict__ b1,
          const float* __restrict__ W2, const float* __restrict__ b2,
          const int* __restrict__ batch,
          float* __restrict__ out, int n) {
    extern __shared__ float smem[];
    float* sW  = smem;                     // 128*128
    float* sIn = sW + 128 * 128;           // 128*FIN
    float* sT  = sIn + 128 * FIN;          // 128*128
    int*   sBatch = (int*)(sT + 128 * 128);

    const int tid  = threadIdx.x;
    const int lane = tid & 31;
    const int wid  = tid >> 5;             // 16 warps
    const int tx   = tid & 31;             // feature group (4 feats)
    const int ty   = tid >> 5;             // node group (8 nodes)
    const int node0 = blockIdx.x * 128;
    const int j0 = tx * 4;
    const int r0 = ty * 8;

    // load W1 (FIN x 128)
    {
        const float4* srcp = (const float4*)W1;
        float4* dstp = (float4*)sW;
        for (int i = tid; i < FIN * 32; i += 512) dstp[i] = srcp[i];
    }
    // batch ids for this tile (clamped; invalid rows contribute zeros anyway)
    if (tid < 128) {
        int node = node0 + tid;
        sBatch[tid] = batch[node < n ? node : (n - 1)];
    }

    // gather prologue: each warp builds 8 rows of sIn
    if (FIN == 128) {
        #pragma unroll
        for (int i = 0; i < 8; i++) {
            int nl = wid * 8 + i;
            int node = node0 + nl;
            float4 acc = make_float4(0.f, 0.f, 0.f, 0.f);
            if (node < n) {
                acc = ((const float4*)src)[node * 32 + lane];
                int s = g_rowptr[node], e = g_rowptr[node + 1];
                for (int j = s; j < e; j++) {
                    float4 v = ((const float4*)src)[g_col[j] * 32 + lane];
                    acc.x += v.x; acc.y += v.y; acc.z += v.z; acc.w += v.w;
                }
            }
            ((float4*)(sIn + nl * 128))[lane] = acc;
        }
    } else {  // FIN == 8
        #pragma unroll
        for (int i = 0; i < 8; i++) {
            int nl = wid * 8 + i;
            int node = node0 + nl;
            if (lane < 8) {
                float acc = 0.f;
                if (node < n) {
                    acc = src[node * 8 + lane];
                    int s = g_rowptr[node], e = g_rowptr[node + 1];
                    for (int j = s; j < e; j++) acc += src[g_col[j] * 8 + lane];
                }
                sIn[nl * 8 + lane] = acc;
            }
        }
    }
    __syncthreads();

    float acc[8][4];
    // ---- stage A: sT = relu(sIn @ W1 + b1) ----
    {
        float4 bb = ((const float4*)b1)[tx];
        #pragma unroll
        for (int i = 0; i < 8; i++) {
            acc[i][0] = bb.x; acc[i][1] = bb.y; acc[i][2] = bb.z; acc[i][3] = bb.w;
        }
        #pragma unroll 4
        for (int k = 0; k < FIN; k++) {
            float4 w = *(const float4*)&sW[k * 128 + j0];
            #pragma unroll
            for (int i = 0; i < 8; i++) {
                float a = sIn[(r0 + i) * FIN + k];
                acc[i][0] += a * w.x;
                acc[i][1] += a * w.y;
                acc[i][2] += a * w.z;
                acc[i][3] += a * w.w;
            }
        }
        #pragma unroll
        for (int i = 0; i < 8; i++) {
            float4 v;
            v.x = fmaxf(acc[i][0], 0.f);
            v.y = fmaxf(acc[i][1], 0.f);
            v.z = fmaxf(acc[i][2], 0.f);
            v.w = fmaxf(acc[i][3], 0.f);
            *(float4*)&sT[(r0 + i) * 128 + j0] = v;
        }
    }
    __syncthreads();

    // load W2 (128 x 128) over W1
    {
        const float4* srcp = (const float4*)W2;
        float4* dstp = (float4*)sW;
        for (int i = tid; i < 128 * 32; i += 512) dstp[i] = srcp[i];
    }
    __syncthreads();

    // ---- stage B: o = relu(sT @ W2 + b2) ----
    {
        float4 bb = ((const float4*)b2)[tx];
        #pragma unroll
        for (int i = 0; i < 8; i++) {
            acc[i][0] = bb.x; acc[i][1] = bb.y; acc[i][2] = bb.z; acc[i][3] = bb.w;
        }
        #pragma unroll 4
        for (int k = 0; k < 128; k++) {
            float4 w = *(const float4*)&sW[k * 128 + j0];
            #pragma unroll
            for (int i = 0; i < 8; i++) {
                float a = sT[(r0 + i) * 128 + k];
                acc[i][0] += a * w.x;
                acc[i][1] += a * w.y;
                acc[i][2] += a * w.z;
                acc[i][3] += a * w.w;
            }
        }
    }
    __syncthreads();  // everyone done READING sT before we overwrite it

    // epilogue: relu, zero invalid rows, optional gmem write, stash in sT
    #pragma unroll
    for (int i = 0; i < 8; i++) {
        int nl = r0 + i;
        int node = node0 + nl;
        float4 v;
        v.x = fmaxf(acc[i][0], 0.f);
        v.y = fmaxf(acc[i][1], 0.f);
        v.z = fmaxf(acc[i][2], 0.f);
        v.w = fmaxf(acc[i][3], 0.f);
        bool valid = node < n;
        if (!valid) v = make_float4(0.f, 0.f, 0.f, 0.f);
        *(float4*)&sT[nl * 128 + j0] = v;
        if (WRITE && valid) ((float4*)out)[node * 32 + tx] = v;
    }
    __syncthreads();

    // pooling: thread f sums its feature column over sorted-batch segments
    if (tid < 128) {
        int f = tid;
        float pacc = sT[f];           // row 0
        int curg = sBatch[0];
        for (int r = 1; r < 128; r++) {
            int g = sBatch[r];
            if (g != curg) {
                atomicAdd(&g_pooled[curg * 384 + SLICE + f], pacc);
                pacc = 0.f;
                curg = g;
            }
            pacc += sT[r * 128 + f];
        }
        atomicAdd(&g_pooled[curg * 384 + SLICE + f], pacc);
    }
}

// ---------------- classifier ----------------
__global__ void cls_kernel(const float* __restrict__ W1, const float* __restrict__ b1,
                           const float* __restrict__ gamma, const float* __restrict__ beta,
                           const float* __restrict__ mean, const float* __restrict__ var,
                           const float* __restrict__ W2, const float* __restrict__ b2,
                           float* __restrict__ out) {
    __shared__ float sp[384];
    __shared__ float sz[256];
    int g = blockIdx.x;
    int tid = threadIdx.x;  // 0..255
    for (int i = tid; i < 384; i += 256) sp[i] = g_pooled[g * 384 + i];
    __syncthreads();
    float acc = b1[tid];
    #pragma unroll 8
    for (int k = 0; k < 384; k++) acc += sp[k] * W1[k * 256 + tid];
    float z = (acc - mean[tid]) * rsqrtf(var[tid] + BN_EPS) * gamma[tid] + beta[tid];
    sz[tid] = fmaxf(z, 0.f);
    __syncthreads();
    if (tid < 4) {
        float o = b2[tid];
        #pragma unroll 8
        for (int k = 0; k < 256; k++) o += sz[k] * W2[k * 4 + tid];
        out[g * 4 + tid] = o;
    }
}

// ---------------- launch ----------------
extern "C" void kernel_launch(void* const* d_in, const int* in_sizes, int n_in,
                              void* d_out, int out_size) {
    const float* x     = (const float*)d_in[0];
    const int*   eidx  = (const int*)d_in[1];
    const int*   batch = (const int*)d_in[2];
    const float* l1_W1 = (const float*)d_in[3];
    const float* l1_b1 = (const float*)d_in[4];
    const float* l1_W2 = (const float*)d_in[5];
    const float* l1_b2 = (const float*)d_in[6];
    const float* l2_W1 = (const float*)d_in[7];
    const float* l2_b1 = (const float*)d_in[8];
    const float* l2_W2 = (const float*)d_in[9];
    const float* l2_b2 = (const float*)d_in[10];
    const float* l3_W1 = (const float*)d_in[11];
    const float* l3_b1 = (const float*)d_in[12];
    const float* l3_W2 = (const float*)d_in[13];
    const float* l3_b2 = (const float*)d_in[14];
    const float* c_W1  = (const float*)d_in[15];
    const float* c_b1  = (const float*)d_in[16];
    const float* bn_g  = (const float*)d_in[17];
    const float* bn_b  = (const float*)d_in[18];
    const float* bn_m  = (const float*)d_in[19];
    const float* bn_v  = (const float*)d_in[20];
    const float* c_W2  = (const float*)d_in[21];
    const float* c_b2  = (const float*)d_in[22];
    float* out = (float*)d_out;

    const int SMEM8   = (128 * 128 + 128 * 8   + 128 * 128) * 4 + 128 * 4;  // 135680
    const int SMEM128 = (128 * 128 + 128 * 128 + 128 * 128) * 4 + 128 * 4;  // 197120
    cudaFuncSetAttribute(mlp_fused<8, 0, true>,
                         cudaFuncAttributeMaxDynamicSharedMemorySize, SMEM8);
    cudaFuncSetAttribute(mlp_fused<128, 128, true>,
                         cudaFuncAttributeMaxDynamicSharedMemorySize, SMEM128);
    cudaFuncSetAttribute(mlp_fused<128, 256, false>,
                         cudaFuncAttributeMaxDynamicSharedMemorySize, SMEM128);

    float* bufA = 0; float* bufB = 0;
    cudaGetSymbolAddress((void**)&bufA, g_bufA);
    cudaGetSymbolAddress((void**)&bufB, g_bufB);

    // init + CSR build
    zero_kernel<<<(NN + 255) / 256, 256>>>();
    count_kernel<<<(NE + 255) / 256, 256>>>(eidx);
    scan_kernel<<<1, 1024>>>();
    fill_kernel<<<(NE + 255) / 256, 256>>>(eidx);

    const int MLP_GRID = (NN + 127) / 128;

    // layer 1: gather(x) -> MLP -> bufA (h1), pool slice 0
    mlp_fused<8, 0, true><<<MLP_GRID, 512, SMEM8>>>(
        x, l1_W1, l1_b1, l1_W2, l1_b2, batch, bufA, NN);
    // layer 2: gather(bufA) -> MLP -> bufB (h2), pool slice 128
    mlp_fused<128, 128, true><<<MLP_GRID, 512, SMEM128>>>(
        bufA, l2_W1, l2_b1, l2_W2, l2_b2, batch, bufB, NN);
    // layer 3: gather(bufB) -> MLP -> pool slice 256 only (h3 not stored)
    mlp_fused<128, 256, false><<<MLP_GRID, 512, SMEM128>>>(
        bufB, l3_W1, l3_b1, l3_W2, l3_b2, batch, nullptr, NN);

    // classifier
    cls_kernel<<<NG, 256>>>(c_W1, c_b1, bn_g, bn_b, bn_m, bn_v, c_W2, c_b2, out);
}

// round 7
// speedup vs baseline: 1.1110x; 1.1110x over previous
#include <cuda_runtime.h>
#include <cuda_bf16.h>
#include <math.h>
#include <stdlib.h>
#include <stdint.h>

#define NN 50000
#define NE 640000
#define NG 64
#define HD 128
#define INF 8
#define BN_EPS 1e-5f

// Best-effort eager module loading (kept from passing R5).
__attribute__((constructor))
static void _set_eager_module_loading() {
    setenv("CUDA_MODULE_LOADING", "EAGER", 1);
}

// ---------------- scratch (static __device__; ~54 MB, same as passing R5) ----
__device__ float g_bufA[NN * HD];          // h1
__device__ float g_bufB[NN * HD];          // h2 (h3 never materialized)
__device__ int   g_deg[NN];
__device__ int   g_rowptr[NN + 1];
__device__ int   g_cursor[NN];
__device__ int   g_col[NE];
__device__ float g_pooled[NG * 384];

namespace {
struct TryEagerLoad {
    TryEagerLoad() { void* p = nullptr; cudaGetSymbolAddress(&p, g_bufA); }
};
static TryEagerLoad _try_eager_load;
}

// ---------------- mma.sync tf32 helpers (portable sm_80+, works on sm_100) ---
__device__ __forceinline__ void mma_tf32(float* c,
        uint32_t a0, uint32_t a1, uint32_t a2, uint32_t a3,
        uint32_t b0, uint32_t b1) {
    asm volatile(
        "mma.sync.aligned.m16n8k8.row.col.f32.tf32.tf32.f32 "
        "{%0,%1,%2,%3}, {%4,%5,%6,%7}, {%8,%9}, {%0,%1,%2,%3};"
        : "+f"(c[0]), "+f"(c[1]), "+f"(c[2]), "+f"(c[3])
        : "r"(a0), "r"(a1), "r"(a2), "r"(a3), "r"(b0), "r"(b1));
}

// 3xTF32 split: x ≈ hi + lo, both tf32-representable fp32 bit patterns.
__device__ __forceinline__ void split_tf32(float x, uint32_t& hi, uint32_t& lo) {
    asm("cvt.rna.tf32.f32 %0, %1;" : "=r"(hi) : "f"(x));
    float r = x - __uint_as_float(hi);
    asm("cvt.rna.tf32.f32 %0, %1;" : "=r"(lo) : "f"(r));
}

// ---------------- init + CSR ----------------
__global__ void zero_kernel() {
    int i = blockIdx.x * blockDim.x + threadIdx.x;
    if (i < NN) g_deg[i] = 0;
    if (i < NG * 384) g_pooled[i] = 0.f;
}

__global__ void count_kernel(const int* __restrict__ eidx) {
    int e = blockIdx.x * blockDim.x + threadIdx.x;
    if (e < NE) atomicAdd(&g_deg[eidx[NE + e]], 1);
}

// single-block shuffle scan over 50000 degrees -> rowptr, cursor(=exclusive)
__global__ void scan_kernel() {
    __shared__ int wsum[32];
    __shared__ int s_carry;
    int tid = threadIdx.x, lane = tid & 31, w = tid >> 5;
    if (tid == 0) { s_carry = 0; g_rowptr[0] = 0; }
    __syncthreads();
    for (int base = 0; base < NN; base += 1024) {
        int i = base + tid;
        int v = (i < NN) ? g_deg[i] : 0;
        int x = v;
        #pragma unroll
        for (int d = 1; d < 32; d <<= 1) {
            int t = __shfl_up_sync(~0u, x, d);
            if (lane >= d) x += t;
        }
        if (lane == 31) wsum[w] = x;
        __syncthreads();
        if (w == 0) {
            int y = wsum[lane];
            #pragma unroll
            for (int d = 1; d < 32; d <<= 1) {
                int t = __shfl_up_sync(~0u, y, d);
                if (lane >= d) y += t;
            }
            wsum[lane] = y;
        }
        __syncthreads();
        int inc = x + (w > 0 ? wsum[w - 1] : 0) + s_carry;
        if (i < NN) { g_rowptr[i + 1] = inc; g_cursor[i] = inc - v; }
        __syncthreads();
        if (tid == 1023) s_carry = inc;
        __syncthreads();
    }
}

__global__ void fill_kernel(const int* __restrict__ eidx) {
    int e = blockIdx.x * blockDim.x + threadIdx.x;
    if (e < NE) {
        int src = eidx[e];
        int dst = eidx[NE + e];
        g_col[atomicAdd(&g_cursor[dst], 1)] = src;
    }
}

// ---------------- fused GIN layer (mma.sync tf32x3) --------------------------
// 512 threads; 128-node tile per block; 16 warps each own a 16x64 output block.
// smem: sW[128][132] | sIn[128][SA] | sT[128][132] | b1s[128] | b2s[128] | batch[128]
template <int FIN, int SLICE, bool WRITE>
__global__ void __launch_bounds__(512, 1)
gin_layer(const float* __restrict__ src,
          const float* __restrict__ W1, const float* __restrict__ b1,
          const float* __restrict__ W2, const float* __restrict__ b2,
          const int* __restrict__ batch,
          float* __restrict__ out, int n) {
    constexpr int SA = (FIN == 128) ? 132 : 12;
    extern __shared__ float smem[];
    float* sW  = smem;                    // 128*132
    float* sIn = sW + 128 * 132;          // 128*SA
    float* sT  = sIn + 128 * SA;          // 128*132
    float* b1s = sT + 128 * 132;
    float* b2s = b1s + 128;
    int*   sBatch = (int*)(b2s + 128);

    const int tid  = threadIdx.x;
    const int lane = tid & 31;
    const int wid  = tid >> 5;            // 16 warps
    const int node0 = blockIdx.x * 128;

    // load W1 [FIN][128] -> sW (stride 132)
    for (int i = tid; i < FIN * 32; i += 512) {
        int k = i >> 5, c = i & 31;
        *(float4*)&sW[k * 132 + c * 4] = ((const float4*)W1)[i];
    }
    if (tid < 128) {
        b1s[tid] = b1[tid];
        b2s[tid] = b2[tid];
        int node = node0 + tid;
        sBatch[tid] = batch[node < n ? node : (n - 1)];
    }

    // gather: sIn[r][:] = src[node] + sum_neighbors
    if (FIN == 128) {
        const float4* src4 = (const float4*)src;
        for (int r = wid; r < 128; r += 16) {
            int node = node0 + r;
            float4 acc = make_float4(0.f, 0.f, 0.f, 0.f);
            if (node < n) {
                acc = src4[node * 32 + lane];
                int s = g_rowptr[node], e = g_rowptr[node + 1];
                for (int j = s; j < e; j++) {
                    float4 v = src4[g_col[j] * 32 + lane];
                    acc.x += v.x; acc.y += v.y; acc.z += v.z; acc.w += v.w;
                }
            }
            *(float4*)&sIn[r * 132 + lane * 4] = acc;
        }
    } else {  // FIN == 8
        const float4* src4 = (const float4*)src;
        for (int r = wid; r < 128; r += 16) {
            if (lane < 2) {
                int node = node0 + r;
                float4 acc = make_float4(0.f, 0.f, 0.f, 0.f);
                if (node < n) {
                    acc = src4[node * 2 + lane];
                    int s = g_rowptr[node], e = g_rowptr[node + 1];
                    for (int j = s; j < e; j++) {
                        float4 v = src4[g_col[j] * 2 + lane];
                        acc.x += v.x; acc.y += v.y; acc.z += v.z; acc.w += v.w;
                    }
                }
                *(float4*)&sIn[r * 12 + lane * 4] = acc;
            }
        }
    }
    __syncthreads();

    // warp tiling: rows [row0, row0+16), cols [col0, col0+64)
    const int row0 = (wid >> 1) * 16;
    const int col0 = (wid & 1) * 64;
    const int qr = lane >> 2;   // 0..7
    const int qc = lane & 3;    // 0..3

    float acc[8][4];

    // ---- stage A: sT = relu(sIn @ W1 + b1) ----
    #pragma unroll
    for (int nt = 0; nt < 8; nt++) {
        int c = col0 + nt * 8 + 2 * qc;
        acc[nt][0] = b1s[c];     acc[nt][1] = b1s[c + 1];
        acc[nt][2] = b1s[c];     acc[nt][3] = b1s[c + 1];
    }
    #pragma unroll
    for (int ks = 0; ks < FIN / 8; ks++) {
        int k0 = ks * 8;
        float a0f = sIn[(row0 + qr)     * SA + k0 + qc];
        float a1f = sIn[(row0 + qr + 8) * SA + k0 + qc];
        float a2f = sIn[(row0 + qr)     * SA + k0 + qc + 4];
        float a3f = sIn[(row0 + qr + 8) * SA + k0 + qc + 4];
        uint32_t ah0, al0, ah1, al1, ah2, al2, ah3, al3;
        split_tf32(a0f, ah0, al0); split_tf32(a1f, ah1, al1);
        split_tf32(a2f, ah2, al2); split_tf32(a3f, ah3, al3);
        #pragma unroll
        for (int nt = 0; nt < 8; nt++) {
            int bn = col0 + nt * 8 + qr;
            float b0f = sW[(k0 + qc)     * 132 + bn];
            float b1f = sW[(k0 + qc + 4) * 132 + bn];
            uint32_t bh0, bl0, bh1, bl1;
            split_tf32(b0f, bh0, bl0); split_tf32(b1f, bh1, bl1);
            mma_tf32(acc[nt], ah0, ah1, ah2, ah3, bh0, bh1);
            mma_tf32(acc[nt], ah0, ah1, ah2, ah3, bl0, bl1);
            mma_tf32(acc[nt], al0, al1, al2, al3, bh0, bh1);
        }
    }
    #pragma unroll
    for (int nt = 0; nt < 8; nt++) {
        int c = col0 + nt * 8 + 2 * qc;
        int r = row0 + qr;
        sT[r * 132 + c]           = fmaxf(acc[nt][0], 0.f);
        sT[r * 132 + c + 1]       = fmaxf(acc[nt][1], 0.f);
        sT[(r + 8) * 132 + c]     = fmaxf(acc[nt][2], 0.f);
        sT[(r + 8) * 132 + c + 1] = fmaxf(acc[nt][3], 0.f);
    }
    __syncthreads();

    // load W2 [128][128] over W1
    for (int i = tid; i < 4096; i += 512) {
        int k = i >> 5, c = i & 31;
        *(float4*)&sW[k * 132 + c * 4] = ((const float4*)W2)[i];
    }
    __syncthreads();

    // ---- stage B: o = relu(sT @ W2 + b2) ----
    #pragma unroll
    for (int nt = 0; nt < 8; nt++) {
        int c = col0 + nt * 8 + 2 * qc;
        acc[nt][0] = b2s[c];     acc[nt][1] = b2s[c + 1];
        acc[nt][2] = b2s[c];     acc[nt][3] = b2s[c + 1];
    }
    #pragma unroll
    for (int ks = 0; ks < 16; ks++) {
        int k0 = ks * 8;
        float a0f = sT[(row0 + qr)     * 132 + k0 + qc];
        float a1f = sT[(row0 + qr + 8) * 132 + k0 + qc];
        float a2f = sT[(row0 + qr)     * 132 + k0 + qc + 4];
        float a3f = sT[(row0 + qr + 8) * 132 + k0 + qc + 4];
        uint32_t ah0, al0, ah1, al1, ah2, al2, ah3, al3;
        split_tf32(a0f, ah0, al0); split_tf32(a1f, ah1, al1);
        split_tf32(a2f, ah2, al2); split_tf32(a3f, ah3, al3);
        #pragma unroll
        for (int nt = 0; nt < 8; nt++) {
            int bn = col0 + nt * 8 + qr;
            float b0f = sW[(k0 + qc)     * 132 + bn];
            float b1f = sW[(k0 + qc + 4) * 132 + bn];
            uint32_t bh0, bl0, bh1, bl1;
            split_tf32(b0f, bh0, bl0); split_tf32(b1f, bh1, bl1);
            mma_tf32(acc[nt], ah0, ah1, ah2, ah3, bh0, bh1);
            mma_tf32(acc[nt], ah0, ah1, ah2, ah3, bl0, bl1);
            mma_tf32(acc[nt], al0, al1, al2, al3, bh0, bh1);
        }
    }
    __syncthreads();  // all sT reads complete before overwrite

    // epilogue: relu, zero invalid rows, stash final tile in sT
    {
        int rA = row0 + qr, rB = row0 + qr + 8;
        bool vA = (node0 + rA) < n, vB = (node0 + rB) < n;
        #pragma unroll
        for (int nt = 0; nt < 8; nt++) {
            int c = col0 + nt * 8 + 2 * qc;
            sT[rA * 132 + c]     = vA ? fmaxf(acc[nt][0], 0.f) : 0.f;
            sT[rA * 132 + c + 1] = vA ? fmaxf(acc[nt][1], 0.f) : 0.f;
            sT[rB * 132 + c]     = vB ? fmaxf(acc[nt][2], 0.f) : 0.f;
            sT[rB * 132 + c + 1] = vB ? fmaxf(acc[nt][3], 0.f) : 0.f;
        }
    }
    __syncthreads();

    // pooling: thread f sums its feature column over sorted-batch segments
    if (tid < 128) {
        int f = tid;
        float pacc = sT[f];
        int curg = sBatch[0];
        for (int r = 1; r < 128; r++) {
            int g = sBatch[r];
            if (g != curg) {
                atomicAdd(&g_pooled[curg * 384 + SLICE + f], pacc);
                pacc = 0.f;
                curg = g;
            }
            pacc += sT[r * 132 + f];
        }
        atomicAdd(&g_pooled[curg * 384 + SLICE + f], pacc);
    }

    // coalesced writeback
    if (WRITE) {
        for (int idx = tid; idx < 128 * 128; idx += 512) {
            int r = idx >> 7, c = idx & 127;
            int node = node0 + r;
            if (node < n) out[node * 128 + c] = sT[r * 132 + c];
        }
    }
}

// ---------------- classifier ----------------
__global__ void cls_kernel(const float* __restrict__ W1, const float* __restrict__ b1,
                           const float* __restrict__ gamma, const float* __restrict__ beta,
                           const float* __restrict__ mean, const float* __restrict__ var,
                           const float* __restrict__ W2, const float* __restrict__ b2,
                           float* __restrict__ out) {
    __shared__ float sp[384];
    __shared__ float sz[256];
    int g = blockIdx.x;
    int tid = threadIdx.x;  // 0..255
    for (int i = tid; i < 384; i += 256) sp[i] = g_pooled[g * 384 + i];
    __syncthreads();
    float acc = b1[tid];
    #pragma unroll 8
    for (int k = 0; k < 384; k++) acc += sp[k] * W1[k * 256 + tid];
    float z = (acc - mean[tid]) * rsqrtf(var[tid] + BN_EPS) * gamma[tid] + beta[tid];
    sz[tid] = fmaxf(z, 0.f);
    __syncthreads();
    if (tid < 4) {
        float o = b2[tid];
        #pragma unroll 8
        for (int k = 0; k < 256; k++) o += sz[k] * W2[k * 4 + tid];
        out[g * 4 + tid] = o;
    }
}

// ---------------- launch ----------------
extern "C" void kernel_launch(void* const* d_in, const int* in_sizes, int n_in,
                              void* d_out, int out_size) {
    const float* x     = (const float*)d_in[0];
    const int*   eidx  = (const int*)d_in[1];
    const int*   batch = (const int*)d_in[2];
    const float* l1_W1 = (const float*)d_in[3];
    const float* l1_b1 = (const float*)d_in[4];
    const float* l1_W2 = (const float*)d_in[5];
    const float* l1_b2 = (const float*)d_in[6];
    const float* l2_W1 = (const float*)d_in[7];
    const float* l2_b1 = (const float*)d_in[8];
    const float* l2_W2 = (const float*)d_in[9];
    const float* l2_b2 = (const float*)d_in[10];
    const float* l3_W1 = (const float*)d_in[11];
    const float* l3_b1 = (const float*)d_in[12];
    const float* l3_W2 = (const float*)d_in[13];
    const float* l3_b2 = (const float*)d_in[14];
    const float* c_W1  = (const float*)d_in[15];
    const float* c_b1  = (const float*)d_in[16];
    const float* bn_g  = (const float*)d_in[17];
    const float* bn_b  = (const float*)d_in[18];
    const float* bn_m  = (const float*)d_in[19];
    const float* bn_v  = (const float*)d_in[20];
    const float* c_W2  = (const float*)d_in[21];
    const float* c_b2  = (const float*)d_in[22];
    float* out = (float*)d_out;

    // smem sizes: sW(128*132) + sIn(128*SA) + sT(128*132) + 2*128 + 128 ints
    const int SMEM128 = (128 * 132 * 2 + 128 * 132 + 256) * 4 + 512;  // 204288
    const int SMEM8   = (128 * 132 * 2 + 128 * 12  + 256) * 4 + 512;  // 142848
    cudaFuncSetAttribute(gin_layer<8, 0, true>,
                         cudaFuncAttributeMaxDynamicSharedMemorySize, SMEM8);
    cudaFuncSetAttribute(gin_layer<128, 128, true>,
                         cudaFuncAttributeMaxDynamicSharedMemorySize, SMEM128);
    cudaFuncSetAttribute(gin_layer<128, 256, false>,
                         cudaFuncAttributeMaxDynamicSharedMemorySize, SMEM128);

    float *bufA, *bufB;
    cudaGetSymbolAddress((void**)&bufA, g_bufA);
    cudaGetSymbolAddress((void**)&bufB, g_bufB);

    // init + CSR
    zero_kernel<<<(NN + 255) / 256, 256>>>();
    count_kernel<<<(NE + 255) / 256, 256>>>(eidx);
    scan_kernel<<<1, 1024>>>();
    fill_kernel<<<(NE + 255) / 256, 256>>>(eidx);

    const int GRID = (NN + 127) / 128;  // 391

    gin_layer<8, 0, true><<<GRID, 512, SMEM8>>>(
        x, l1_W1, l1_b1, l1_W2, l1_b2, batch, bufA, NN);
    gin_layer<128, 128, true><<<GRID, 512, SMEM128>>>(
        bufA, l2_W1, l2_b1, l2_W2, l2_b2, batch, bufB, NN);
    gin_layer<128, 256, false><<<GRID, 512, SMEM128>>>(
        bufB, l3_W1, l3_b1, l3_W2, l3_b2, batch, nullptr, NN);

    cls_kernel<<<NG, 256>>>(c_W1, c_b1, bn_g, bn_b, bn_m, bn_v, c_W2, c_b2, out);
}